// round 2
// baseline (speedup 1.0000x reference)
#include <cuda_runtime.h>

#define NHEADS 8
#define TQ 4
#define QH 16
#define QW 16
#define TK 4
#define KH 16
#define KW 16
#define DIM 64

#define PS 68          // padded smem row stride in floats (272B: 16B-aligned, bank-skewed)
#define NQ 32768       // 4*8*4*16*16 total queries
#define RELW 36        // per-query rel values: H[16], W[16], T[4]

// 4.7 MB scratch for rel values: layout [q][36] = relH[0..15], relW[16..31], relT[32..35]
__device__ float g_rel[NQ * RELW];

// ---------------------------------------------------------------------------
// Kernel 1: compute all rel dot-products.
// One block per (b*N, t, h): stages 16 query vectors + needed embedding rows,
// computes 16*36 = 576 dots (64-dim) with float4 smem reads + 4 accumulators.
// ---------------------------------------------------------------------------
__global__ __launch_bounds__(256, 8)
void rel_kernel(const float* __restrict__ query,
                const float* __restrict__ Hemb,   // [31,64]
                const float* __restrict__ Wemb,   // [31,64]
                const float* __restrict__ Temb)   // [7,64]
{
    __shared__ float sQ[QW][PS];
    __shared__ float sH[KH][PS];
    __shared__ float sW[31][PS];
    __shared__ float sT[TK][PS];

    const int bid = blockIdx.x;          // ((b*8+N)*4 + t)*16 + h
    const int h   = bid & 15;
    const int t   = (bid >> 4) & 3;
    const int bn  = bid >> 6;
    const int tid = threadIdx.x;

    const int qbase = bn * 1024 + t * 256 + h * 16;   // first of 16 queries

    // stage 16 query vectors (contiguous 4KB)
    const float* qsrc = query + (size_t)qbase * DIM;
    for (int i = tid; i < QW * DIM; i += 256) {
        sQ[i >> 6][i & 63] = qsrc[i];
    }
    // sH[kh] = Hemb[h - kh + 15]
    for (int i = tid; i < KH * DIM; i += 256) {
        sH[i >> 6][i & 63] = Hemb[(h + 15 - (i >> 6)) * DIM + (i & 63)];
    }
    // full W table
    for (int i = tid; i < 31 * DIM; i += 256) {
        sW[i >> 6][i & 63] = Wemb[i];
    }
    // sT[kt] = Temb[t - kt + 3]
    for (int i = tid; i < TK * DIM; i += 256) {
        sT[i >> 6][i & 63] = Temb[(t + 3 - (i >> 6)) * DIM + (i & 63)];
    }
    __syncthreads();

    // 576 dots: d -> (w, jj)
    for (int d = tid; d < QW * RELW; d += 256) {
        int w  = d / RELW;
        int jj = d - w * RELW;
        const float* tab;
        if (jj < 16)      tab = sH[jj];
        else if (jj < 32) tab = sW[w - (jj - 16) + 15];
        else              tab = sT[jj - 32];

        const float4* qv4 = (const float4*)sQ[w];
        const float4* tb4 = (const float4*)tab;
        float a0 = 0.f, a1 = 0.f, a2 = 0.f, a3 = 0.f;
        #pragma unroll
        for (int c = 0; c < DIM / 4; c += 4) {
            float4 q0 = qv4[c],     t0 = tb4[c];
            float4 q1 = qv4[c + 1], t1 = tb4[c + 1];
            float4 q2 = qv4[c + 2], t2 = tb4[c + 2];
            float4 q3 = qv4[c + 3], t3 = tb4[c + 3];
            a0 += q0.x*t0.x + q0.y*t0.y + q0.z*t0.z + q0.w*t0.w;
            a1 += q1.x*t1.x + q1.y*t1.y + q1.z*t1.z + q1.w*t1.w;
            a2 += q2.x*t2.x + q2.y*t2.y + q2.z*t2.z + q2.w*t2.w;
            a3 += q3.x*t3.x + q3.y*t3.y + q3.z*t3.z + q3.w*t3.w;
        }
        g_rel[(size_t)(qbase + w) * RELW + jj] = (a0 + a1) + (a2 + a3);
    }
}

// ---------------------------------------------------------------------------
// Kernel 2: pure stream. One block per 16 output rows (128KB in+out).
// Stage 576 rel floats into smem, one barrier, then unrolled float4 stream.
// ---------------------------------------------------------------------------
#define SRS 40   // smem rel row stride (160B: 16B-aligned so relW float4 loads work)

__global__ __launch_bounds__(256)
void stream_kernel(const float* __restrict__ scores,
                   float* __restrict__ out)
{
    __shared__ float sRel[QW][SRS];

    const int bid = blockIdx.x;          // same mapping as rel_kernel
    const int tid = threadIdx.x;
    const int qbase = (bid >> 6) * 1024 + ((bid >> 4) & 3) * 256 + (bid & 15) * 16;

    // stage 16 queries x 36 rel values (contiguous 2304B in gmem)
    const float* relsrc = g_rel + (size_t)qbase * RELW;
    for (int i = tid; i < QW * RELW; i += 256) {
        int w = i / RELW;
        sRel[w][i - w * RELW] = relsrc[i];
    }
    __syncthreads();

    // per-thread fixed position within a 1024-wide row
    const int kt  = tid >> 6;            // constant across warp
    const int kh  = (tid >> 2) & 15;
    const int kw4 = (tid & 3) << 2;

    const size_t rowbase = (size_t)qbase * 1024;
    const float4* sc4 = (const float4*)(scores + rowbase);
    float4*       ot4 = (float4*)(out + rowbase);

    #pragma unroll 8
    for (int w = 0; w < QW; w++) {
        int v = (w << 8) + tid;
        float4 s = sc4[v];
        float base = sRel[w][kh] + sRel[w][32 + kt];
        float4 rw = *(const float4*)&sRel[w][16 + kw4];
        s.x += base + rw.x;
        s.y += base + rw.y;
        s.z += base + rw.z;
        s.w += base + rw.w;
        ot4[v] = s;
    }
}

extern "C" void kernel_launch(void* const* d_in, const int* in_sizes, int n_in,
                              void* d_out, int out_size) {
    const float* query  = (const float*)d_in[0];
    const float* scores = (const float*)d_in[1];
    const float* Hemb   = (const float*)d_in[2];
    const float* Wemb   = (const float*)d_in[3];
    const float* Temb   = (const float*)d_in[4];
    float* out = (float*)d_out;

    rel_kernel<<<2048, 256>>>(query, Hemb, Wemb, Temb);
    stream_kernel<<<2048, 256>>>(scores, out);
}